// round 13
// baseline (speedup 1.0000x reference)
#include <cuda_runtime.h>

// Problem constants
#define B_      64
#define S_      512
#define EMB_    300
#define T_      16
#define K4_     75          // EMB_/4
#define C_      32          // chunks per batch
#define CS_     16          // steps per chunk
#define FULL_   0xffffffffu
#define LN16_   2.7725887222397811f

// Packed f32x2 helpers
#define FMA2(d, a, b, c) asm("fma.rn.f32x2 %0, %1, %2, %3;" : "=l"(d) : "l"(a), "l"(b), "l"(c))
#define MUL2b(d, a, b)   asm("mul.rn.f32x2 %0, %1, %2;"     : "=l"(d) : "l"(a), "l"(b))
#define ADD2(d, a, b)    asm("add.rn.f32x2 %0, %1, %2;"     : "=l"(d) : "l"(a), "l"(b))
#define PACK2(d, lo, hi) asm("mov.b64 %0, {%1, %2};"        : "=l"(d) : "f"(lo), "f"(hi))

__device__ __forceinline__ float2 unpack2(unsigned long long v) {
    float2 f;
    asm("mov.b64 {%0, %1}, %2;" : "=f"(f.x), "=f"(f.y) : "l"(v));
    return f;
}

// Scratch: per-(batch,chunk) transfer matrices, transposed:
// g_M[m*256 + j*16 + i] = M_m[i][j]
__device__ float g_M[B_ * C_ * 256];

// ---------------------------------------------------------------------------
// Kernel 1: probs = embed[text] @ W + b.
// 512 threads, 32 tokens/block, 2 tokens/warp: lanes 0-15 -> token A,
// 16-31 -> token B, j = lane&15.  W in static SMEM (19.2 KB -> 2 blocks/SM,
// 32 warps).  e rows read by broadcast LDG.128 straight from L2/DRAM,
// BATCHED 5 deep (MLP=5); W via batched conflict-free LDS.128.
// Two f32x2 accumulator chains per lane.
// ---------------------------------------------------------------------------
__global__ void __launch_bounds__(512, 2) probs_kernel(const int*   __restrict__ text,
                                                       const float* __restrict__ embed,
                                                       const float* __restrict__ W,
                                                       const float* __restrict__ bias,
                                                       float*       __restrict__ probs) {
    __shared__ ulonglong2 W4s[K4_ * T_];   // W4s[k*16+j] = (W[4k..4k+3][j])
    __shared__ float      bsh[T_];

    int tid = threadIdx.x;
    {
        float* wf = (float*)W4s;
        for (int idx = tid; idx < EMB_ * T_; idx += 512) {
            int d = idx >> 4, j = idx & 15;
            wf[((d >> 2) * T_ + j) * 4 + (d & 3)] = W[idx];
        }
        if (tid < T_) bsh[tid] = bias[tid];
    }
    __syncthreads();

    int warp = tid >> 5, lane = tid & 31;
    int half = lane >> 4, j = lane & 15;
    int token = blockIdx.x * 32 + warp * 2 + half;

    const ulonglong2* erow =
        (const ulonglong2*)(embed + (size_t)text[token] * EMB_);

    unsigned long long accA = 0ull, accB = 0ull;

    #pragma unroll 1
    for (int g = 0; g < 15; g++) {
        int k0 = g * 5;
        // batched loads: 5 e (broadcast LDG.128, contiguous -> L1 reuse), 5 W
        ulonglong2 e0 = erow[k0 + 0];
        ulonglong2 e1 = erow[k0 + 1];
        ulonglong2 e2 = erow[k0 + 2];
        ulonglong2 e3 = erow[k0 + 3];
        ulonglong2 e4 = erow[k0 + 4];
        ulonglong2 w0 = W4s[(k0 + 0) * T_ + j];
        ulonglong2 w1 = W4s[(k0 + 1) * T_ + j];
        ulonglong2 w2 = W4s[(k0 + 2) * T_ + j];
        ulonglong2 w3 = W4s[(k0 + 3) * T_ + j];
        ulonglong2 w4 = W4s[(k0 + 4) * T_ + j];

        FMA2(accA, e0.x, w0.x, accA);
        FMA2(accB, e0.y, w0.y, accB);
        FMA2(accA, e1.x, w1.x, accA);
        FMA2(accB, e1.y, w1.y, accB);
        FMA2(accA, e2.x, w2.x, accA);
        FMA2(accB, e2.y, w2.y, accB);
        FMA2(accA, e3.x, w3.x, accA);
        FMA2(accB, e3.y, w3.y, accB);
        FMA2(accA, e4.x, w4.x, accA);
        FMA2(accB, e4.y, w4.y, accB);
    }

    ADD2(accA, accA, accB);
    float2 f = unpack2(accA);
    probs[(size_t)token * T_ + j] = f.x + f.y + bsh[j];
}

// ---------------------------------------------------------------------------
// Kernel 2: per-(batch,chunk) transfer-matrix products.
// grid 256 x 128: 8 matrices per block (half-warp per matrix).
// ---------------------------------------------------------------------------
__global__ void __launch_bounds__(128) chunk_kernel(const int*   __restrict__ text,
                                                    const float* __restrict__ probs,
                                                    const float* __restrict__ trans) {
    __shared__ float Esh[256];       // Esh[j*16+k] = exp(trans[k][j])
    __shared__ float psh[4][512];

    int tid = threadIdx.x;
    for (int idx = tid; idx < 256; idx += 128) {
        int k = idx >> 4, jj = idx & 15;
        Esh[jj * 16 + k] = __expf(trans[idx]);
    }

    int warp = tid >> 5, lane = tid & 31;
    int half = lane >> 4, li = lane & 15;
    int m = blockIdx.x * 8 + warp * 2 + half;
    int b = m >> 5, c = m & (C_ - 1);

    // len for batch b
    const int4* tx4 = (const int4*)(text + b * S_);
    int cnt = 0;
    #pragma unroll
    for (int q = 0; q < 8; q++) {
        int4 v = tx4[li + q * 16];
        cnt += (v.x != 0) + (v.y != 0) + (v.z != 0) + (v.w != 0);
    }
    #pragma unroll
    for (int o = 8; o; o >>= 1) cnt += __shfl_xor_sync(FULL_, cnt, o);
    int len = cnt;

    // Stage exp(emit)/16 for this chunk's 16 steps
    {
        const float4* p4 = (const float4*)(probs + ((size_t)b * S_ + c * CS_) * T_);
        float* myp = &psh[warp][half * 256];
        #pragma unroll
        for (int q = 0; q < 4; q++) {
            float4 v = p4[li + q * 16];
            int o4 = (li + q * 16) * 4;
            myp[o4 + 0] = __expf(v.x) * 0.0625f;
            myp[o4 + 1] = __expf(v.y) * 0.0625f;
            myp[o4 + 2] = __expf(v.z) * 0.0625f;
            myp[o4 + 3] = __expf(v.w) * 0.0625f;
        }
    }
    __syncthreads();

    float M[16];
    #pragma unroll
    for (int jj = 0; jj < 16; jj++) M[jj] = (jj == li) ? 1.f : 0.f;

    const float* myp = &psh[warp][half * 256];
    #pragma unroll 1
    for (int dt = 0; dt < CS_; dt++) {
        int t = c * CS_ + dt;
        if (t >= 1 && t < len) {
            const float4* pv = (const float4*)(myp + dt * 16);
            float4 pa = pv[0], pb = pv[1], pc = pv[2], pd = pv[3];
            float p[16] = {pa.x, pa.y, pa.z, pa.w,  pb.x, pb.y, pb.z, pb.w,
                           pc.x, pc.y, pc.z, pc.w,  pd.x, pd.y, pd.z, pd.w};
            unsigned long long mp[8];
            #pragma unroll
            for (int q = 0; q < 8; q++) PACK2(mp[q], M[2 * q], M[2 * q + 1]);
            float N[16];
            #pragma unroll
            for (int jj = 0; jj < 16; jj++) {
                const ulonglong2* e2 = (const ulonglong2*)(Esh + jj * 16);
                ulonglong2 ea = e2[0], eb = e2[1], ec = e2[2], ed = e2[3];
                unsigned long long a0, a1;
                MUL2b(a0, mp[0], ea.x);
                FMA2(a0, mp[1], ea.y, a0);
                FMA2(a0, mp[2], eb.x, a0);
                FMA2(a0, mp[3], eb.y, a0);
                MUL2b(a1, mp[4], ec.x);
                FMA2(a1, mp[5], ec.y, a1);
                FMA2(a1, mp[6], ed.x, a1);
                FMA2(a1, mp[7], ed.y, a1);
                ADD2(a0, a0, a1);
                float2 f = unpack2(a0);
                N[jj] = (f.x + f.y) * p[jj];
            }
            #pragma unroll
            for (int jj = 0; jj < 16; jj++) M[jj] = N[jj];
        }
    }

    float* out = g_M + (size_t)m * 256 + li;
    #pragma unroll
    for (int jj = 0; jj < 16; jj++) out[jj * 16] = M[jj];
}

// ---------------------------------------------------------------------------
// Kernel 3: combine + scores.  256 threads per batch row.
// Warp 0: serial combine over 32 chunk matrices (prefetched from L2).
// Warps 1-7: unary+binary scores in parallel.  Lens via ballot.
// ---------------------------------------------------------------------------
__global__ void __launch_bounds__(256) combine_kernel(const int*   __restrict__ text,
                                                      const int*   __restrict__ tags,
                                                      const float* __restrict__ probs,
                                                      const float* __restrict__ trans,
                                                      float*       __restrict__ out_lens,
                                                      float*       __restrict__ out_ll) {
    __shared__ float sA[16];
    __shared__ float scp[8];
    __shared__ int   cnt[8];

    int tid  = threadIdx.x;
    int warp = tid >> 5, lane = tid & 31;
    int b    = blockIdx.x;

    // lens via ballot: thread covers s = tid and s = tid + 256
    {
        unsigned b0 = __ballot_sync(FULL_, text[b * S_ + tid] != 0);
        unsigned b1 = __ballot_sync(FULL_, text[b * S_ + tid + 256] != 0);
        if (lane == 0) cnt[warp] = __popc(b0) + __popc(b1);
    }
    __syncthreads();
    int len = 0;
    #pragma unroll
    for (int q = 0; q < 8; q++) len += cnt[q];

    const float* pb = probs + (size_t)b * S_ * T_;

    if (warp == 0) {
        int j = lane & 15;
        float a[16];
        {
            const float4* p4 = (const float4*)pb;
            #pragma unroll
            for (int q = 0; q < 4; q++) {
                float4 v = p4[q];
                a[4*q+0] = v.x; a[4*q+1] = v.y; a[4*q+2] = v.z; a[4*q+3] = v.w;
            }
        }
        float mx = a[0];
        #pragma unroll
        for (int i = 1; i < 16; i++) mx = fmaxf(mx, a[i]);
        float L = mx;
        #pragma unroll
        for (int i = 0; i < 16; i++) a[i] = __expf(a[i] - mx);

        const ulonglong2* MT = (const ulonglong2*)(g_M + (size_t)b * C_ * 256);
        ulonglong2 mc[4];
        #pragma unroll
        for (int q = 0; q < 4; q++) mc[q] = MT[j * 4 + q];

        #pragma unroll 1
        for (int c = 0; c < C_; c++) {
            ulonglong2 mn[4];
            if (c + 1 < C_) {
                #pragma unroll
                for (int q = 0; q < 4; q++) mn[q] = MT[(c + 1) * 64 + j * 4 + q];
            }
            int t0 = (c == 0) ? 1 : c * CS_;
            int hi = c * CS_ + CS_ - 1;
            int te = (len - 1 < hi) ? len - 1 : hi;
            int n  = te - t0 + 1;
            if (n > 0) {
                unsigned long long ap[8];
                #pragma unroll
                for (int q = 0; q < 8; q++) PACK2(ap[q], a[2*q], a[2*q+1]);
                unsigned long long a0, a1;
                MUL2b(a0, ap[0], mc[0].x);
                FMA2(a0, ap[1], mc[0].y, a0);
                FMA2(a0, ap[2], mc[1].x, a0);
                FMA2(a0, ap[3], mc[1].y, a0);
                MUL2b(a1, ap[4], mc[2].x);
                FMA2(a1, ap[5], mc[2].y, a1);
                FMA2(a1, ap[6], mc[3].x, a1);
                FMA2(a1, ap[7], mc[3].y, a1);
                ADD2(a0, a0, a1);
                float2 f = unpack2(a0);
                if (lane < 16) sA[j] = f.x + f.y;
                __syncwarp();
                {
                    const float4* s4 = (const float4*)sA;
                    #pragma unroll
                    for (int q = 0; q < 4; q++) {
                        float4 v = s4[q];
                        a[4*q+0] = v.x; a[4*q+1] = v.y;
                        a[4*q+2] = v.z; a[4*q+3] = v.w;
                    }
                }
                __syncwarp();
                float mm = a[0];
                #pragma unroll
                for (int i = 1; i < 16; i++) mm = fmaxf(mm, a[i]);
                float r = __frcp_rn(mm);
                #pragma unroll
                for (int i = 0; i < 16; i++) a[i] *= r;
                L += __logf(mm) + (float)n * LN16_;
            }
            #pragma unroll
            for (int q = 0; q < 4; q++) mc[q] = mn[q];
        }
        float ssum = 0.f;
        #pragma unroll
        for (int i = 0; i < 16; i++) ssum += a[i];
        if (lane == 0) scp[0] = -(L + __logf(ssum));
    } else {
        // scores: t = tid-32 in 0..223 covers s = t, t+224, (t<64: t+448)
        const int* tg = tags + b * S_;
        float sc = 0.f;
        int t = tid - 32;
        {
            int s = t;
            if (s < len) {
                int tg1 = tg[s];
                sc += pb[s * T_ + tg1];
                if (s >= 1) sc += trans[tg[s - 1] * T_ + tg1];
            }
        }
        {
            int s = t + 224;
            if (s < len) {
                int tg1 = tg[s];
                sc += pb[s * T_ + tg1];
                sc += trans[tg[s - 1] * T_ + tg1];
            }
        }
        if (t < 64) {
            int s = t + 448;
            if (s < len) {
                int tg1 = tg[s];
                sc += pb[s * T_ + tg1];
                sc += trans[tg[s - 1] * T_ + tg1];
            }
        }
        #pragma unroll
        for (int o = 16; o; o >>= 1) sc += __shfl_xor_sync(FULL_, sc, o);
        if (lane == 0) scp[warp] = sc;
    }
    __syncthreads();

    if (tid == 0) {
        float tot = 0.f;
        #pragma unroll
        for (int q = 0; q < 8; q++) tot += scp[q];
        out_ll[b]   = tot;
        out_lens[b] = (float)len;
    }
}

// ---------------------------------------------------------------------------
// Launch.  Output layout: probs [0,524288) | lens [524288,524352) | ll [...)
// ---------------------------------------------------------------------------
extern "C" void kernel_launch(void* const* d_in, const int* in_sizes, int n_in,
                              void* d_out, int out_size) {
    const int*   text  = (const int*)  d_in[0];
    const int*   tags  = (const int*)  d_in[1];
    const float* embed = (const float*)d_in[2];
    const float* W     = (const float*)d_in[3];
    const float* bias  = (const float*)d_in[4];
    const float* trans = (const float*)d_in[5];

    float* out      = (float*)d_out;
    float* probs    = out;
    float* out_lens = out + B_ * S_ * T_;
    float* out_ll   = out_lens + B_;

    probs_kernel  <<<(B_ * S_) / 32, 512>>>(text, embed, W, bias, probs);
    chunk_kernel  <<<(B_ * C_) / 8, 128>>>(text, probs, trans);
    combine_kernel<<<B_, 256>>>(text, tags, probs, trans, out_lens, out_ll);
}